// round 4
// baseline (speedup 1.0000x reference)
#include <cuda_runtime.h>
#include <cstdint>

// BatchedHGNNLayer: out = diag(Dv^-1/2) H diag(De^-1) H^T diag(Dv^-1/2) x W^T + b
// B=8, N=4096, E=2048, C=128 (fp32)

#define B_ 8
#define N_ 4096
#define E_ 2048
#define C_ 128
#define EPS 1e-6f

// ---------------- scratch (device globals; no cudaMalloc allowed) ----------
__device__ float g_DvInv[B_ * N_];          // rsqrt(node degree)
__device__ float g_DeP[8][B_ * E_];         // partial column sums (deterministic 2-stage)
__device__ float g_De[B_ * E_];             // edge degree (+eps)
__device__ float g_M[B_ * E_ * C_];         // intermediate  De^-1 H^T Xs
__device__ float g_Y[(size_t)B_ * N_ * C_]; // intermediate  H M * DvInv
__device__ float g_Wt[C_ * C_];             // W^T

// ---------------- degree kernels -------------------------------------------
__global__ void dv_kernel(const float* __restrict__ Hg) {
    // one warp per row; blockDim (32,8); grid B_*N_/8
    int row = blockIdx.x * 8 + threadIdx.y;
    const float4* h4 = (const float4*)(Hg + (size_t)row * E_);
    float s = 0.f;
    for (int i = threadIdx.x; i < E_ / 4; i += 32) {
        float4 v = h4[i];
        s += (v.x + v.y) + (v.z + v.w);
    }
    #pragma unroll
    for (int o = 16; o; o >>= 1) s += __shfl_xor_sync(0xffffffffu, s, o);
    if (threadIdx.x == 0) g_DvInv[row] = rsqrtf(s + EPS);
}

__global__ void de_part_kernel(const float* __restrict__ Hg) {
    // grid (E_/128, 8 splits, B_), block 128
    int e = blockIdx.x * 128 + threadIdx.x;
    int b = blockIdx.z;
    int s = blockIdx.y;
    const float* p = Hg + ((size_t)b * N_ + (size_t)s * 512) * E_ + e;
    float a0 = 0.f, a1 = 0.f, a2 = 0.f, a3 = 0.f;
    #pragma unroll 4
    for (int n = 0; n < 512; n += 4) {
        a0 += p[(size_t)(n + 0) * E_];
        a1 += p[(size_t)(n + 1) * E_];
        a2 += p[(size_t)(n + 2) * E_];
        a3 += p[(size_t)(n + 3) * E_];
    }
    g_DeP[s][b * E_ + e] = (a0 + a1) + (a2 + a3);
}

__global__ void de_reduce_kernel() {
    int i = blockIdx.x * 256 + threadIdx.x;   // B_*E_ = 16384 threads
    float s = EPS;
    #pragma unroll
    for (int k = 0; k < 8; k++) s += g_DeP[k][i];
    g_De[i] = s;
}

__global__ void wt_kernel(const float* __restrict__ W) {
    int idx = blockIdx.x * 256 + threadIdx.x; // 16384
    int j = idx >> 7, k = idx & 127;
    g_Wt[k * C_ + j] = W[idx];
}

// ---------------- GEMM1: M[b,e,c] = (1/De) * sum_n H[b,n,e] * x[b,n,c]*DvInv[b,n]
// A = H^T tile loads are naturally k-major/contiguous. BM=128(e) BN=128(c) BK=16.
__global__ __launch_bounds__(256) void gemm1_kernel(const float* __restrict__ Hg,
                                                    const float* __restrict__ xg) {
    const int b  = blockIdx.z;
    const int e0 = blockIdx.x * 128;
    const float* Hb = Hg + (size_t)b * N_ * E_;
    const float* xb = xg + (size_t)b * N_ * C_;
    const float* dv = g_DvInv + b * N_;

    __shared__ float As[2][16][132];
    __shared__ float Bs[2][16][128];

    const int tid = threadIdx.x;
    const int tx = tid & 15, ty = tid >> 4;

    float acc[8][8];
    #pragma unroll
    for (int i = 0; i < 8; i++)
        #pragma unroll
        for (int j = 0; j < 8; j++) acc[i][j] = 0.f;

    float4 ra[2], rb[2];

    #define G1_LOAD(n0)                                                        \
        _Pragma("unroll")                                                      \
        for (int i = 0; i < 2; i++) {                                          \
            int f = tid + i * 256;                                             \
            int k = f >> 5, q = f & 31;                                        \
            ra[i] = *(const float4*)(Hb + (size_t)((n0) + k) * E_ + e0 + q*4); \
            float s = dv[(n0) + k];                                            \
            float4 v = *(const float4*)(xb + (size_t)((n0) + k) * C_ + q*4);   \
            v.x *= s; v.y *= s; v.z *= s; v.w *= s;                            \
            rb[i] = v;                                                         \
        }
    #define G1_STORE(buf)                                                      \
        _Pragma("unroll")                                                      \
        for (int i = 0; i < 2; i++) {                                          \
            int f = tid + i * 256;                                             \
            int k = f >> 5, q = f & 31;                                        \
            *(float4*)&As[buf][k][q * 4] = ra[i];                              \
            *(float4*)&Bs[buf][k][q * 4] = rb[i];                              \
        }

    G1_LOAD(0); G1_STORE(0); __syncthreads();
    const int KT = N_ / 16;
    for (int kt = 0; kt < KT; ++kt) {
        int cur = kt & 1;
        if (kt + 1 < KT) { G1_LOAD((kt + 1) * 16); }
        #pragma unroll
        for (int kk = 0; kk < 16; kk++) {
            float a[8], bb[8];
            *(float4*)&a[0]  = *(const float4*)&As[cur][kk][ty * 4];
            *(float4*)&a[4]  = *(const float4*)&As[cur][kk][64 + ty * 4];
            *(float4*)&bb[0] = *(const float4*)&Bs[cur][kk][tx * 4];
            *(float4*)&bb[4] = *(const float4*)&Bs[cur][kk][64 + tx * 4];
            #pragma unroll
            for (int i = 0; i < 8; i++)
                #pragma unroll
                for (int j = 0; j < 8; j++) acc[i][j] += a[i] * bb[j];
        }
        if (kt + 1 < KT) { G1_STORE(cur ^ 1); }
        __syncthreads();
    }

    float* Mb = g_M + (size_t)b * E_ * C_;
    #pragma unroll
    for (int i = 0; i < 8; i++) {
        int e = e0 + ((i < 4) ? (ty * 4 + i) : (64 + ty * 4 + (i - 4)));
        float s = 1.0f / g_De[b * E_ + e];
        float4 v0 = make_float4(acc[i][0]*s, acc[i][1]*s, acc[i][2]*s, acc[i][3]*s);
        float4 v1 = make_float4(acc[i][4]*s, acc[i][5]*s, acc[i][6]*s, acc[i][7]*s);
        *(float4*)(Mb + (size_t)e * C_ + tx * 4)      = v0;
        *(float4*)(Mb + (size_t)e * C_ + 64 + tx * 4) = v1;
    }
}

// ---------------- GEMM2: Y[b,n,c] = DvInv[b,n] * sum_e H[b,n,e] * M[b,e,c]
// A = H, normal layout -> transpose-on-load into As[k][m].
__global__ __launch_bounds__(256) void gemm2_kernel(const float* __restrict__ Hg) {
    const int b  = blockIdx.z;
    const int n0 = blockIdx.x * 128;
    const float* Hb = Hg + (size_t)b * N_ * E_;
    const float* Mb = g_M + (size_t)b * E_ * C_;
    const float* dv = g_DvInv + b * N_;

    __shared__ float As[2][16][132];
    __shared__ float Bs[2][16][128];

    const int tid = threadIdx.x;
    const int tx = tid & 15, ty = tid >> 4;

    float acc[8][8];
    #pragma unroll
    for (int i = 0; i < 8; i++)
        #pragma unroll
        for (int j = 0; j < 8; j++) acc[i][j] = 0.f;

    float4 ra[2], rb[2];

    #define G2_LOAD(k0)                                                        \
        _Pragma("unroll")                                                      \
        for (int i = 0; i < 2; i++) {                                          \
            int f = tid + i * 256;                                             \
            int m = f >> 2, q = f & 3;                                         \
            ra[i] = *(const float4*)(Hb + (size_t)(n0 + m) * E_ + (k0) + q*4); \
            int k = f >> 5, c = f & 31;                                        \
            rb[i] = *(const float4*)(Mb + (size_t)((k0) + k) * C_ + c * 4);    \
        }
    #define G2_STORE(buf)                                                      \
        _Pragma("unroll")                                                      \
        for (int i = 0; i < 2; i++) {                                          \
            int f = tid + i * 256;                                             \
            int m = f >> 2, q = f & 3;                                         \
            As[buf][q * 4 + 0][m] = ra[i].x;                                   \
            As[buf][q * 4 + 1][m] = ra[i].y;                                   \
            As[buf][q * 4 + 2][m] = ra[i].z;                                   \
            As[buf][q * 4 + 3][m] = ra[i].w;                                   \
            int k = f >> 5, c = f & 31;                                        \
            *(float4*)&Bs[buf][k][c * 4] = rb[i];                              \
        }

    G2_LOAD(0); G2_STORE(0); __syncthreads();
    const int KT = E_ / 16;
    for (int kt = 0; kt < KT; ++kt) {
        int cur = kt & 1;
        if (kt + 1 < KT) { G2_LOAD((kt + 1) * 16); }
        #pragma unroll
        for (int kk = 0; kk < 16; kk++) {
            float a[8], bb[8];
            *(float4*)&a[0]  = *(const float4*)&As[cur][kk][ty * 4];
            *(float4*)&a[4]  = *(const float4*)&As[cur][kk][64 + ty * 4];
            *(float4*)&bb[0] = *(const float4*)&Bs[cur][kk][tx * 4];
            *(float4*)&bb[4] = *(const float4*)&Bs[cur][kk][64 + tx * 4];
            #pragma unroll
            for (int i = 0; i < 8; i++)
                #pragma unroll
                for (int j = 0; j < 8; j++) acc[i][j] += a[i] * bb[j];
        }
        if (kt + 1 < KT) { G2_STORE(cur ^ 1); }
        __syncthreads();
    }

    float* Yb = g_Y + (size_t)b * N_ * C_;
    #pragma unroll
    for (int i = 0; i < 8; i++) {
        int n = n0 + ((i < 4) ? (ty * 4 + i) : (64 + ty * 4 + (i - 4)));
        float s = dv[n];
        float4 v0 = make_float4(acc[i][0]*s, acc[i][1]*s, acc[i][2]*s, acc[i][3]*s);
        float4 v1 = make_float4(acc[i][4]*s, acc[i][5]*s, acc[i][6]*s, acc[i][7]*s);
        *(float4*)(Yb + (size_t)n * C_ + tx * 4)      = v0;
        *(float4*)(Yb + (size_t)n * C_ + 64 + tx * 4) = v1;
    }
}

// ---------------- GEMM3 (linear): out[r,j] = sum_k Y[r,k]*Wt[k,j] + bias[j]
__global__ __launch_bounds__(256) void gemm3_kernel(const float* __restrict__ bias,
                                                    float* __restrict__ outp) {
    const int r0 = blockIdx.x * 128;   // flattened B*N rows

    __shared__ float As[2][16][132];
    __shared__ float Bs[2][16][128];

    const int tid = threadIdx.x;
    const int tx = tid & 15, ty = tid >> 4;

    float acc[8][8];
    #pragma unroll
    for (int i = 0; i < 8; i++)
        #pragma unroll
        for (int j = 0; j < 8; j++) acc[i][j] = 0.f;

    float4 ra[2], rb[2];

    #define G3_LOAD(k0)                                                          \
        _Pragma("unroll")                                                        \
        for (int i = 0; i < 2; i++) {                                            \
            int f = tid + i * 256;                                               \
            int m = f >> 2, q = f & 3;                                           \
            ra[i] = *(const float4*)(g_Y + (size_t)(r0 + m) * C_ + (k0) + q*4);  \
            int k = f >> 5, c = f & 31;                                          \
            rb[i] = *(const float4*)(g_Wt + (size_t)((k0) + k) * C_ + c * 4);    \
        }
    #define G3_STORE(buf)                                                        \
        _Pragma("unroll")                                                        \
        for (int i = 0; i < 2; i++) {                                            \
            int f = tid + i * 256;                                               \
            int m = f >> 2, q = f & 3;                                           \
            As[buf][q * 4 + 0][m] = ra[i].x;                                     \
            As[buf][q * 4 + 1][m] = ra[i].y;                                     \
            As[buf][q * 4 + 2][m] = ra[i].z;                                     \
            As[buf][q * 4 + 3][m] = ra[i].w;                                     \
            int k = f >> 5, c = f & 31;                                          \
            *(float4*)&Bs[buf][k][c * 4] = rb[i];                                \
        }

    G3_LOAD(0); G3_STORE(0); __syncthreads();
    const int KT = C_ / 16;  // 8
    for (int kt = 0; kt < KT; ++kt) {
        int cur = kt & 1;
        if (kt + 1 < KT) { G3_LOAD((kt + 1) * 16); }
        #pragma unroll
        for (int kk = 0; kk < 16; kk++) {
            float a[8], bb[8];
            *(float4*)&a[0]  = *(const float4*)&As[cur][kk][ty * 4];
            *(float4*)&a[4]  = *(const float4*)&As[cur][kk][64 + ty * 4];
            *(float4*)&bb[0] = *(const float4*)&Bs[cur][kk][tx * 4];
            *(float4*)&bb[4] = *(const float4*)&Bs[cur][kk][64 + tx * 4];
            #pragma unroll
            for (int i = 0; i < 8; i++)
                #pragma unroll
                for (int j = 0; j < 8; j++) acc[i][j] += a[i] * bb[j];
        }
        if (kt + 1 < KT) { G3_STORE(cur ^ 1); }
        __syncthreads();
    }

    float bi0[4], bi1[4];
    *(float4*)bi0 = *(const float4*)(bias + tx * 4);
    *(float4*)bi1 = *(const float4*)(bias + 64 + tx * 4);
    #pragma unroll
    for (int i = 0; i < 8; i++) {
        int r = r0 + ((i < 4) ? (ty * 4 + i) : (64 + ty * 4 + (i - 4)));
        float4 v0 = make_float4(acc[i][0]+bi0[0], acc[i][1]+bi0[1],
                                acc[i][2]+bi0[2], acc[i][3]+bi0[3]);
        float4 v1 = make_float4(acc[i][4]+bi1[0], acc[i][5]+bi1[1],
                                acc[i][6]+bi1[2], acc[i][7]+bi1[3]);
        *(float4*)(outp + (size_t)r * C_ + tx * 4)      = v0;
        *(float4*)(outp + (size_t)r * C_ + 64 + tx * 4) = v1;
    }
}

// ---------------- launch ----------------------------------------------------
extern "C" void kernel_launch(void* const* d_in, const int* in_sizes, int n_in,
                              void* d_out, int out_size) {
    // Identify inputs by element count (robust to metadata ordering):
    const float *x = nullptr, *H = nullptr, *W = nullptr, *bias = nullptr;
    for (int i = 0; i < n_in; i++) {
        long long s = in_sizes[i];
        if (s == (long long)B_ * N_ * E_)      H = (const float*)d_in[i];
        else if (s == (long long)B_ * N_ * C_) x = (const float*)d_in[i];
        else if (s == (long long)C_ * C_)      W = (const float*)d_in[i];
        else if (s == (long long)C_)           bias = (const float*)d_in[i];
    }
    float* outp = (float*)d_out;

    // degrees + weight transpose
    dv_kernel<<<B_ * N_ / 8, dim3(32, 8)>>>(H);
    de_part_kernel<<<dim3(E_ / 128, 8, B_), 128>>>(H);
    de_reduce_kernel<<<B_ * E_ / 256, 256>>>();
    wt_kernel<<<C_ * C_ / 256, 256>>>(W);

    // M = De^-1 H^T (Dv^-1/2 x)
    gemm1_kernel<<<dim3(E_ / 128, 1, B_), 256>>>(H, x);
    // Y = Dv^-1/2 (H M)
    gemm2_kernel<<<dim3(N_ / 128, 1, B_), 256>>>(H);
    // out = Y W^T + b
    gemm3_kernel<<<(B_ * N_) / 128, 256>>>(bias, outp);
}

// round 5
// speedup vs baseline: 2.0914x; 2.0914x over previous
#include <cuda_runtime.h>
#include <cstdint>

// BatchedHGNNLayer: out = diag(Dv^-1/2) H diag(De^-1) H^T diag(Dv^-1/2) x W^T + b
// B=8, N=4096, E=2048, C=128 (fp32), TF32 tensor-core path.

#define B_ 8
#define N_ 4096
#define E_ 2048
#define C_ 128
#define EPS 1e-6f

// ---------------- scratch (device globals; no cudaMalloc allowed) ----------
__device__ float g_DvInv[B_ * N_];           // rsqrt(node degree)
__device__ float g_M[B_ * E_ * C_];          // De^-1 H^T (Dv^-1/2 x)
__device__ float g_M2[B_ * E_ * C_];         // M · W^T
__device__ float g_Wt[C_ * C_];              // W^T

// ---------------- helpers ---------------------------------------------------
__device__ __forceinline__ float tf32r(float x) {
    uint32_t u;
    asm("cvt.rna.tf32.f32 %0, %1;" : "=r"(u) : "f"(x));
    return __uint_as_float(u);
}

__device__ __forceinline__ void mma_tf32(float* c, const uint32_t* a, const uint32_t* b) {
    asm volatile(
        "mma.sync.aligned.m16n8k8.row.col.f32.tf32.tf32.f32 "
        "{%0,%1,%2,%3}, {%4,%5,%6,%7}, {%8,%9}, {%0,%1,%2,%3};"
        : "+f"(c[0]), "+f"(c[1]), "+f"(c[2]), "+f"(c[3])
        : "r"(a[0]), "r"(a[1]), "r"(a[2]), "r"(a[3]), "r"(b[0]), "r"(b[1]));
}

// Warp-tile compute: BM=128, BN=128, BK=16; 8 warps in 2(m) x 4(n);
// warp tile 64x32 = 4x4 of m16n8k8.  As/Bs stride 136 -> conflict-free frags.
#define MMA_TILE(cur)                                                           \
    _Pragma("unroll")                                                           \
    for (int ks = 0; ks < 16; ks += 8) {                                        \
        uint32_t af[4][4], bf[4][2];                                            \
        _Pragma("unroll")                                                       \
        for (int mt = 0; mt < 4; mt++) {                                        \
            int m = wm * 64 + mt * 16 + g;                                      \
            af[mt][0] = __float_as_uint(As[cur][ks + tg][m]);                   \
            af[mt][1] = __float_as_uint(As[cur][ks + tg][m + 8]);               \
            af[mt][2] = __float_as_uint(As[cur][ks + 4 + tg][m]);               \
            af[mt][3] = __float_as_uint(As[cur][ks + 4 + tg][m + 8]);           \
        }                                                                       \
        _Pragma("unroll")                                                       \
        for (int nt = 0; nt < 4; nt++) {                                        \
            int n = wn * 32 + nt * 8 + g;                                       \
            bf[nt][0] = __float_as_uint(Bs[cur][ks + tg][n]);                   \
            bf[nt][1] = __float_as_uint(Bs[cur][ks + 4 + tg][n]);               \
        }                                                                       \
        _Pragma("unroll")                                                       \
        for (int mt = 0; mt < 4; mt++)                                          \
            _Pragma("unroll")                                                   \
            for (int nt = 0; nt < 4; nt++)                                      \
                mma_tf32(acc[mt][nt], af[mt], bf[nt]);                          \
    }

// ---------------- degree kernel (Dv) ----------------------------------------
__global__ void dv_kernel(const float* __restrict__ Hg) {
    int row = blockIdx.x * 8 + threadIdx.y;
    const float4* h4 = (const float4*)(Hg + (size_t)row * E_);
    float s = 0.f;
    for (int i = threadIdx.x; i < E_ / 4; i += 32) {
        float4 v = h4[i];
        s += (v.x + v.y) + (v.z + v.w);
    }
    #pragma unroll
    for (int o = 16; o; o >>= 1) s += __shfl_xor_sync(0xffffffffu, s, o);
    if (threadIdx.x == 0) g_DvInv[row] = rsqrtf(s + EPS);
}

__global__ void wt_kernel(const float* __restrict__ W) {
    int idx = blockIdx.x * 256 + threadIdx.x;
    int j = idx >> 7, k = idx & 127;
    g_Wt[k * C_ + j] = W[idx];
}

// ---------------- GEMM1: M[b,e,c] = De^-1 * sum_n H[b,n,e] * x[b,n,c]*DvInv[b,n]
// De computed inline from the same H stream.
__global__ __launch_bounds__(256) void gemm1_kernel(const float* __restrict__ Hg,
                                                    const float* __restrict__ xg) {
    const int b  = blockIdx.z;
    const int e0 = blockIdx.x * 128;
    const float* Hb = Hg + (size_t)b * N_ * E_;
    const float* xb = xg + (size_t)b * N_ * C_;
    const float* dv = g_DvInv + b * N_;

    __shared__ float As[2][16][136];
    __shared__ float Bs[2][16][136];
    __shared__ float deP[8][128];
    __shared__ float deInv[128];

    const int tid = threadIdx.x;
    const int wid = tid >> 5, lane = tid & 31;
    const int g = lane >> 2, tg = lane & 3;
    const int wm = wid & 1, wn = wid >> 1;

    float acc[4][4][4];
    #pragma unroll
    for (int i = 0; i < 4; i++)
        #pragma unroll
        for (int j = 0; j < 4; j++)
            #pragma unroll
            for (int r = 0; r < 4; r++) acc[i][j][r] = 0.f;

    float4 ra[2], rb[2];
    float4 deS[2];
    deS[0] = make_float4(0.f, 0.f, 0.f, 0.f);
    deS[1] = make_float4(0.f, 0.f, 0.f, 0.f);

    #define G1_LOAD(n0)                                                          \
        _Pragma("unroll")                                                        \
        for (int i = 0; i < 2; i++) {                                            \
            int f = tid + i * 256;                                               \
            int k = f >> 5, q = f & 31;                                          \
            float4 h = *(const float4*)(Hb + (size_t)((n0) + k) * E_ + e0 + q*4);\
            deS[i].x += h.x; deS[i].y += h.y; deS[i].z += h.z; deS[i].w += h.w;  \
            ra[i] = h;                                                           \
            float s = __ldg(dv + (n0) + k);                                      \
            float4 v = *(const float4*)(xb + (size_t)((n0) + k) * C_ + q*4);     \
            v.x *= s; v.y *= s; v.z *= s; v.w *= s;                              \
            rb[i] = v;                                                           \
        }
    #define G1_STORE(buf)                                                        \
        _Pragma("unroll")                                                        \
        for (int i = 0; i < 2; i++) {                                            \
            int f = tid + i * 256;                                               \
            int k = f >> 5, q = f & 31;                                          \
            float4 a = ra[i], v = rb[i];                                         \
            a.x = tf32r(a.x); a.y = tf32r(a.y); a.z = tf32r(a.z); a.w = tf32r(a.w);\
            v.x = tf32r(v.x); v.y = tf32r(v.y); v.z = tf32r(v.z); v.w = tf32r(v.w);\
            *(float4*)&As[buf][k][q * 4] = a;                                    \
            *(float4*)&Bs[buf][k][q * 4] = v;                                    \
        }

    G1_LOAD(0); G1_STORE(0); __syncthreads();
    const int KT = N_ / 16;
    for (int kt = 0; kt < KT; ++kt) {
        int cur = kt & 1;
        if (kt + 1 < KT) { G1_LOAD((kt + 1) * 16); }
        MMA_TILE(cur);
        if (kt + 1 < KT) { G1_STORE(cur ^ 1); }
        __syncthreads();
    }

    // De reduction (exact fp32, fixed order -> deterministic)
    {
        float4 s = make_float4(deS[0].x + deS[1].x, deS[0].y + deS[1].y,
                               deS[0].z + deS[1].z, deS[0].w + deS[1].w);
        *(float4*)&deP[tid >> 5][(tid & 31) * 4] = s;
    }
    __syncthreads();
    if (tid < 128) {
        float t = EPS;
        #pragma unroll
        for (int j = 0; j < 8; j++) t += deP[j][tid];
        deInv[tid] = 1.0f / t;
    }
    __syncthreads();

    float* Mb = g_M + (size_t)b * E_ * C_;
    #pragma unroll
    for (int mt = 0; mt < 4; mt++) {
        int r0 = wm * 64 + mt * 16 + g;
        float sa = deInv[r0], sb = deInv[r0 + 8];
        #pragma unroll
        for (int nt = 0; nt < 4; nt++) {
            int col = wn * 32 + nt * 8 + tg * 2;
            float2 v0 = make_float2(acc[mt][nt][0] * sa, acc[mt][nt][1] * sa);
            float2 v1 = make_float2(acc[mt][nt][2] * sb, acc[mt][nt][3] * sb);
            *(float2*)(Mb + (size_t)(e0 + r0) * C_ + col)     = v0;
            *(float2*)(Mb + (size_t)(e0 + r0 + 8) * C_ + col) = v1;
        }
    }
}

// ---------------- GEMM1b: M2 = M · W^T   (rows = B*E, K = C = 128)
__global__ __launch_bounds__(256) void gemm1b_kernel() {
    const int r0 = blockIdx.x * 128;

    __shared__ float As[2][16][136];
    __shared__ float Bs[2][16][136];

    const int tid = threadIdx.x;
    const int wid = tid >> 5, lane = tid & 31;
    const int g = lane >> 2, tg = lane & 3;
    const int wm = wid & 1, wn = wid >> 1;

    float acc[4][4][4];
    #pragma unroll
    for (int i = 0; i < 4; i++)
        #pragma unroll
        for (int j = 0; j < 4; j++)
            #pragma unroll
            for (int r = 0; r < 4; r++) acc[i][j][r] = 0.f;

    float4 ra[2], rb[2];

    #define G1B_LOAD(k0)                                                         \
        _Pragma("unroll")                                                        \
        for (int i = 0; i < 2; i++) {                                            \
            int f = tid + i * 256;                                               \
            int m = f >> 2, q = f & 3;                                           \
            ra[i] = *(const float4*)(g_M + (size_t)(r0 + m) * C_ + (k0) + q*4);  \
            int k = f >> 5, c = f & 31;                                          \
            rb[i] = *(const float4*)(g_Wt + (size_t)((k0) + k) * C_ + c * 4);    \
        }
    #define G1B_STORE(buf)                                                       \
        _Pragma("unroll")                                                        \
        for (int i = 0; i < 2; i++) {                                            \
            int f = tid + i * 256;                                               \
            int m = f >> 2, q = f & 3;                                           \
            As[buf][q * 4 + 0][m] = tf32r(ra[i].x);                              \
            As[buf][q * 4 + 1][m] = tf32r(ra[i].y);                              \
            As[buf][q * 4 + 2][m] = tf32r(ra[i].z);                              \
            As[buf][q * 4 + 3][m] = tf32r(ra[i].w);                              \
            int k = f >> 5, c = f & 31;                                          \
            float4 v = rb[i];                                                    \
            v.x = tf32r(v.x); v.y = tf32r(v.y); v.z = tf32r(v.z); v.w = tf32r(v.w);\
            *(float4*)&Bs[buf][k][c * 4] = v;                                    \
        }

    G1B_LOAD(0); G1B_STORE(0); __syncthreads();
    const int KT = C_ / 16;
    for (int kt = 0; kt < KT; ++kt) {
        int cur = kt & 1;
        if (kt + 1 < KT) { G1B_LOAD((kt + 1) * 16); }
        MMA_TILE(cur);
        if (kt + 1 < KT) { G1B_STORE(cur ^ 1); }
        __syncthreads();
    }

    #pragma unroll
    for (int mt = 0; mt < 4; mt++) {
        int rr = wm * 64 + mt * 16 + g;
        #pragma unroll
        for (int nt = 0; nt < 4; nt++) {
            int col = wn * 32 + nt * 8 + tg * 2;
            float2 v0 = make_float2(acc[mt][nt][0], acc[mt][nt][1]);
            float2 v1 = make_float2(acc[mt][nt][2], acc[mt][nt][3]);
            *(float2*)(g_M2 + (size_t)(r0 + rr) * C_ + col)     = v0;
            *(float2*)(g_M2 + (size_t)(r0 + rr + 8) * C_ + col) = v1;
        }
    }
}

// ---------------- GEMM2: out[b,n,c] = DvInv[b,n] * sum_e H[b,n,e]*M2[b,e,c] + bias[c]
__global__ __launch_bounds__(256) void gemm2_kernel(const float* __restrict__ Hg,
                                                    const float* __restrict__ bias,
                                                    float* __restrict__ outp) {
    const int b  = blockIdx.z;
    const int n0 = blockIdx.x * 128;
    const float* Hb = Hg + (size_t)b * N_ * E_;
    const float* Mb = g_M2 + (size_t)b * E_ * C_;

    __shared__ float As[2][16][136];
    __shared__ float Bs[2][16][136];
    __shared__ float dvS[128];
    __shared__ float biasS[128];

    const int tid = threadIdx.x;
    const int wid = tid >> 5, lane = tid & 31;
    const int g = lane >> 2, tg = lane & 3;
    const int wm = wid & 1, wn = wid >> 1;

    if (tid < 128) {
        dvS[tid]   = g_DvInv[b * N_ + n0 + tid];
        biasS[tid] = bias[tid];
    }

    float acc[4][4][4];
    #pragma unroll
    for (int i = 0; i < 4; i++)
        #pragma unroll
        for (int j = 0; j < 4; j++)
            #pragma unroll
            for (int r = 0; r < 4; r++) acc[i][j][r] = 0.f;

    float4 ra[2], rb[2];

    #define G2_LOAD(k0)                                                          \
        _Pragma("unroll")                                                        \
        for (int i = 0; i < 2; i++) {                                            \
            int f = tid + i * 256;                                               \
            int m = f >> 2, q = f & 3;                                           \
            ra[i] = *(const float4*)(Hb + (size_t)(n0 + m) * E_ + (k0) + q*4);   \
            int k = f >> 5, c = f & 31;                                          \
            rb[i] = *(const float4*)(Mb + (size_t)((k0) + k) * C_ + c * 4);      \
        }
    #define G2_STORE(buf)                                                        \
        _Pragma("unroll")                                                        \
        for (int i = 0; i < 2; i++) {                                            \
            int f = tid + i * 256;                                               \
            int m = f >> 2, q = f & 3;                                           \
            As[buf][q * 4 + 0][m] = tf32r(ra[i].x);                              \
            As[buf][q * 4 + 1][m] = tf32r(ra[i].y);                              \
            As[buf][q * 4 + 2][m] = tf32r(ra[i].z);                              \
            As[buf][q * 4 + 3][m] = tf32r(ra[i].w);                              \
            int k = f >> 5, c = f & 31;                                          \
            float4 v = rb[i];                                                    \
            v.x = tf32r(v.x); v.y = tf32r(v.y); v.z = tf32r(v.z); v.w = tf32r(v.w);\
            *(float4*)&Bs[buf][k][c * 4] = v;                                    \
        }

    G2_LOAD(0); G2_STORE(0); __syncthreads();
    const int KT = E_ / 16;
    for (int kt = 0; kt < KT; ++kt) {
        int cur = kt & 1;
        if (kt + 1 < KT) { G2_LOAD((kt + 1) * 16); }
        MMA_TILE(cur);
        if (kt + 1 < KT) { G2_STORE(cur ^ 1); }
        __syncthreads();
    }

    float* Ob = outp + (size_t)b * N_ * C_;
    #pragma unroll
    for (int mt = 0; mt < 4; mt++) {
        int rr = wm * 64 + mt * 16 + g;
        float sa = dvS[rr], sb = dvS[rr + 8];
        #pragma unroll
        for (int nt = 0; nt < 4; nt++) {
            int col = wn * 32 + nt * 8 + tg * 2;
            float b0 = biasS[col], b1 = biasS[col + 1];
            float2 v0 = make_float2(acc[mt][nt][0] * sa + b0, acc[mt][nt][1] * sa + b1);
            float2 v1 = make_float2(acc[mt][nt][2] * sb + b0, acc[mt][nt][3] * sb + b1);
            *(float2*)(Ob + (size_t)(n0 + rr) * C_ + col)     = v0;
            *(float2*)(Ob + (size_t)(n0 + rr + 8) * C_ + col) = v1;
        }
    }
}

// ---------------- launch ----------------------------------------------------
extern "C" void kernel_launch(void* const* d_in, const int* in_sizes, int n_in,
                              void* d_out, int out_size) {
    const float *x = nullptr, *H = nullptr, *W = nullptr, *bias = nullptr;
    for (int i = 0; i < n_in; i++) {
        long long s = in_sizes[i];
        if (s == (long long)B_ * N_ * E_)      H = (const float*)d_in[i];
        else if (s == (long long)B_ * N_ * C_) x = (const float*)d_in[i];
        else if (s == (long long)C_ * C_)      W = (const float*)d_in[i];
        else if (s == (long long)C_)           bias = (const float*)d_in[i];
    }
    float* outp = (float*)d_out;

    dv_kernel<<<B_ * N_ / 8, dim3(32, 8)>>>(H);
    wt_kernel<<<C_ * C_ / 256, 256>>>(W);

    // M = De^-1 H^T (Dv^-1/2 x), De fused
    gemm1_kernel<<<dim3(E_ / 128, 1, B_), 256>>>(H, x);
    // M2 = M W^T
    gemm1b_kernel<<<(B_ * E_) / 128, 256>>>();
    // out = Dv^-1/2 (H M2) + b
    gemm2_kernel<<<dim3(N_ / 128, 1, B_), 256>>>(H, bias, outp);
}

// round 6
// speedup vs baseline: 2.1014x; 1.0048x over previous
#include <cuda_runtime.h>
#include <cstdint>

// BatchedHGNNLayer: out = diag(Dv^-1/2) H diag(De^-1) H^T diag(Dv^-1/2) x W^T + b
// B=8, N=4096, E=2048, C=128 (fp32), TF32 tensor-core path.

#define B_ 8
#define N_ 4096
#define E_ 2048
#define C_ 128
#define EPS 1e-6f

// ---------------- scratch (device globals; no cudaMalloc allowed) ----------
__device__ float g_DvInv[B_ * N_];           // rsqrt(node degree)
__device__ float g_M[B_ * E_ * C_];          // De^-1 H^T (Dv^-1/2 x)
__device__ float g_M2[B_ * E_ * C_];         // M · W^T
__device__ float g_Wt[C_ * C_];              // W^T

// ---------------- helpers ---------------------------------------------------
__device__ __forceinline__ float tf32r(float x) {
    uint32_t u;
    asm("cvt.rna.tf32.f32 %0, %1;" : "=r"(u) : "f"(x));
    return __uint_as_float(u);
}

__device__ __forceinline__ void mma_tf32(float* c, const uint32_t* a, const uint32_t* b) {
    asm volatile(
        "mma.sync.aligned.m16n8k8.row.col.f32.tf32.tf32.f32 "
        "{%0,%1,%2,%3}, {%4,%5,%6,%7}, {%8,%9}, {%0,%1,%2,%3};"
        : "+f"(c[0]), "+f"(c[1]), "+f"(c[2]), "+f"(c[3])
        : "r"(a[0]), "r"(a[1]), "r"(a[2]), "r"(a[3]), "r"(b[0]), "r"(b[1]));
}

// Warp-tile compute: BM=128, BN=128, BK=16; 8 warps in 2(m) x 4(n);
// warp tile 64x32 = 4x4 of m16n8k8.  As/Bs stride 136 -> conflict-free frags.
#define MMA_TILE(cur)                                                           \
    _Pragma("unroll")                                                           \
    for (int ks = 0; ks < 16; ks += 8) {                                        \
        uint32_t af[4][4], bf[4][2];                                            \
        _Pragma("unroll")                                                       \
        for (int mt = 0; mt < 4; mt++) {                                        \
            int m = wm * 64 + mt * 16 + g;                                      \
            af[mt][0] = __float_as_uint(As[cur][ks + tg][m]);                   \
            af[mt][1] = __float_as_uint(As[cur][ks + tg][m + 8]);               \
            af[mt][2] = __float_as_uint(As[cur][ks + 4 + tg][m]);               \
            af[mt][3] = __float_as_uint(As[cur][ks + 4 + tg][m + 8]);           \
        }                                                                       \
        _Pragma("unroll")                                                       \
        for (int nt = 0; nt < 4; nt++) {                                        \
            int n = wn * 32 + nt * 8 + g;                                       \
            bf[nt][0] = __float_as_uint(Bs[cur][ks + tg][n]);                   \
            bf[nt][1] = __float_as_uint(Bs[cur][ks + 4 + tg][n]);               \
        }                                                                       \
        _Pragma("unroll")                                                       \
        for (int mt = 0; mt < 4; mt++)                                          \
            _Pragma("unroll")                                                   \
            for (int nt = 0; nt < 4; nt++)                                      \
                mma_tf32(acc[mt][nt], af[mt], bf[nt]);                          \
    }

// ---------------- degree kernel (Dv) ----------------------------------------
__global__ void dv_kernel(const float* __restrict__ Hg) {
    int row = blockIdx.x * 8 + threadIdx.y;
    const float4* h4 = (const float4*)(Hg + (size_t)row * E_);
    float s = 0.f;
    for (int i = threadIdx.x; i < E_ / 4; i += 32) {
        float4 v = h4[i];
        s += (v.x + v.y) + (v.z + v.w);
    }
    #pragma unroll
    for (int o = 16; o; o >>= 1) s += __shfl_xor_sync(0xffffffffu, s, o);
    if (threadIdx.x == 0) g_DvInv[row] = rsqrtf(s + EPS);
}

__global__ void wt_kernel(const float* __restrict__ W) {
    int idx = blockIdx.x * 256 + threadIdx.x;
    int j = idx >> 7, k = idx & 127;
    g_Wt[k * C_ + j] = W[idx];
}

// ---------------- GEMM1: M[b,e,c] = De^-1 * sum_n H[b,n,e] * x[b,n,c]*DvInv[b,n]
// De computed inline from the same H stream.
__global__ __launch_bounds__(256) void gemm1_kernel(const float* __restrict__ Hg,
                                                    const float* __restrict__ xg) {
    const int b  = blockIdx.z;
    const int e0 = blockIdx.x * 128;
    const float* Hb = Hg + (size_t)b * N_ * E_;
    const float* xb = xg + (size_t)b * N_ * C_;
    const float* dv = g_DvInv + b * N_;

    __shared__ float As[2][16][136];
    __shared__ float Bs[2][16][136];
    __shared__ float deP[8][128];
    __shared__ float deInv[128];

    const int tid = threadIdx.x;
    const int wid = tid >> 5, lane = tid & 31;
    const int g = lane >> 2, tg = lane & 3;
    const int wm = wid & 1, wn = wid >> 1;

    float acc[4][4][4];
    #pragma unroll
    for (int i = 0; i < 4; i++)
        #pragma unroll
        for (int j = 0; j < 4; j++)
            #pragma unroll
            for (int r = 0; r < 4; r++) acc[i][j][r] = 0.f;

    float4 ra[2], rb[2];
    float4 deS[2];
    deS[0] = make_float4(0.f, 0.f, 0.f, 0.f);
    deS[1] = make_float4(0.f, 0.f, 0.f, 0.f);

    #define G1_LOAD(n0)                                                          \
        _Pragma("unroll")                                                        \
        for (int i = 0; i < 2; i++) {                                            \
            int f = tid + i * 256;                                               \
            int k = f >> 5, q = f & 31;                                          \
            float4 h = *(const float4*)(Hb + (size_t)((n0) + k) * E_ + e0 + q*4);\
            deS[i].x += h.x; deS[i].y += h.y; deS[i].z += h.z; deS[i].w += h.w;  \
            ra[i] = h;                                                           \
            float s = __ldg(dv + (n0) + k);                                      \
            float4 v = *(const float4*)(xb + (size_t)((n0) + k) * C_ + q*4);     \
            v.x *= s; v.y *= s; v.z *= s; v.w *= s;                              \
            rb[i] = v;                                                           \
        }
    #define G1_STORE(buf)                                                        \
        _Pragma("unroll")                                                        \
        for (int i = 0; i < 2; i++) {                                            \
            int f = tid + i * 256;                                               \
            int k = f >> 5, q = f & 31;                                          \
            float4 a = ra[i], v = rb[i];                                         \
            a.x = tf32r(a.x); a.y = tf32r(a.y); a.z = tf32r(a.z); a.w = tf32r(a.w);\
            v.x = tf32r(v.x); v.y = tf32r(v.y); v.z = tf32r(v.z); v.w = tf32r(v.w);\
            *(float4*)&As[buf][k][q * 4] = a;                                    \
            *(float4*)&Bs[buf][k][q * 4] = v;                                    \
        }

    G1_LOAD(0); G1_STORE(0); __syncthreads();
    const int KT = N_ / 16;
    for (int kt = 0; kt < KT; ++kt) {
        int cur = kt & 1;
        if (kt + 1 < KT) { G1_LOAD((kt + 1) * 16); }
        MMA_TILE(cur);
        if (kt + 1 < KT) { G1_STORE(cur ^ 1); }
        __syncthreads();
    }

    // De reduction (exact fp32, fixed order -> deterministic)
    {
        float4 s = make_float4(deS[0].x + deS[1].x, deS[0].y + deS[1].y,
                               deS[0].z + deS[1].z, deS[0].w + deS[1].w);
        *(float4*)&deP[tid >> 5][(tid & 31) * 4] = s;
    }
    __syncthreads();
    if (tid < 128) {
        float t = EPS;
        #pragma unroll
        for (int j = 0; j < 8; j++) t += deP[j][tid];
        deInv[tid] = 1.0f / t;
    }
    __syncthreads();

    float* Mb = g_M + (size_t)b * E_ * C_;
    #pragma unroll
    for (int mt = 0; mt < 4; mt++) {
        int r0 = wm * 64 + mt * 16 + g;
        float sa = deInv[r0], sb = deInv[r0 + 8];
        #pragma unroll
        for (int nt = 0; nt < 4; nt++) {
            int col = wn * 32 + nt * 8 + tg * 2;
            float2 v0 = make_float2(acc[mt][nt][0] * sa, acc[mt][nt][1] * sa);
            float2 v1 = make_float2(acc[mt][nt][2] * sb, acc[mt][nt][3] * sb);
            *(float2*)(Mb + (size_t)(e0 + r0) * C_ + col)     = v0;
            *(float2*)(Mb + (size_t)(e0 + r0 + 8) * C_ + col) = v1;
        }
    }
}

// ---------------- GEMM1b: M2 = M · W^T   (rows = B*E, K = C = 128)
__global__ __launch_bounds__(256) void gemm1b_kernel() {
    const int r0 = blockIdx.x * 128;

    __shared__ float As[2][16][136];
    __shared__ float Bs[2][16][136];

    const int tid = threadIdx.x;
    const int wid = tid >> 5, lane = tid & 31;
    const int g = lane >> 2, tg = lane & 3;
    const int wm = wid & 1, wn = wid >> 1;

    float acc[4][4][4];
    #pragma unroll
    for (int i = 0; i < 4; i++)
        #pragma unroll
        for (int j = 0; j < 4; j++)
            #pragma unroll
            for (int r = 0; r < 4; r++) acc[i][j][r] = 0.f;

    float4 ra[2], rb[2];

    #define G1B_LOAD(k0)                                                         \
        _Pragma("unroll")                                                        \
        for (int i = 0; i < 2; i++) {                                            \
            int f = tid + i * 256;                                               \
            int m = f >> 2, q = f & 3;                                           \
            ra[i] = *(const float4*)(g_M + (size_t)(r0 + m) * C_ + (k0) + q*4);  \
            int k = f >> 5, c = f & 31;                                          \
            rb[i] = *(const float4*)(g_Wt + (size_t)((k0) + k) * C_ + c * 4);    \
        }
    #define G1B_STORE(buf)                                                       \
        _Pragma("unroll")                                                        \
        for (int i = 0; i < 2; i++) {                                            \
            int f = tid + i * 256;                                               \
            int m = f >> 2, q = f & 3;                                           \
            As[buf][q * 4 + 0][m] = tf32r(ra[i].x);                              \
            As[buf][q * 4 + 1][m] = tf32r(ra[i].y);                              \
            As[buf][q * 4 + 2][m] = tf32r(ra[i].z);                              \
            As[buf][q * 4 + 3][m] = tf32r(ra[i].w);                              \
            int k = f >> 5, c = f & 31;                                          \
            float4 v = rb[i];                                                    \
            v.x = tf32r(v.x); v.y = tf32r(v.y); v.z = tf32r(v.z); v.w = tf32r(v.w);\
            *(float4*)&Bs[buf][k][c * 4] = v;                                    \
        }

    G1B_LOAD(0); G1B_STORE(0); __syncthreads();
    const int KT = C_ / 16;
    for (int kt = 0; kt < KT; ++kt) {
        int cur = kt & 1;
        if (kt + 1 < KT) { G1B_LOAD((kt + 1) * 16); }
        MMA_TILE(cur);
        if (kt + 1 < KT) { G1B_STORE(cur ^ 1); }
        __syncthreads();
    }

    #pragma unroll
    for (int mt = 0; mt < 4; mt++) {
        int rr = wm * 64 + mt * 16 + g;
        #pragma unroll
        for (int nt = 0; nt < 4; nt++) {
            int col = wn * 32 + nt * 8 + tg * 2;
            float2 v0 = make_float2(acc[mt][nt][0], acc[mt][nt][1]);
            float2 v1 = make_float2(acc[mt][nt][2], acc[mt][nt][3]);
            *(float2*)(g_M2 + (size_t)(r0 + rr) * C_ + col)     = v0;
            *(float2*)(g_M2 + (size_t)(r0 + rr + 8) * C_ + col) = v1;
        }
    }
}

// ---------------- GEMM2: out[b,n,c] = DvInv[b,n] * sum_e H[b,n,e]*M2[b,e,c] + bias[c]
__global__ __launch_bounds__(256) void gemm2_kernel(const float* __restrict__ Hg,
                                                    const float* __restrict__ bias,
                                                    float* __restrict__ outp) {
    const int b  = blockIdx.z;
    const int n0 = blockIdx.x * 128;
    const float* Hb = Hg + (size_t)b * N_ * E_;
    const float* Mb = g_M2 + (size_t)b * E_ * C_;

    __shared__ float As[2][16][136];
    __shared__ float Bs[2][16][136];
    __shared__ float dvS[128];
    __shared__ float biasS[128];

    const int tid = threadIdx.x;
    const int wid = tid >> 5, lane = tid & 31;
    const int g = lane >> 2, tg = lane & 3;
    const int wm = wid & 1, wn = wid >> 1;

    if (tid < 128) {
        dvS[tid]   = g_DvInv[b * N_ + n0 + tid];
        biasS[tid] = bias[tid];
    }

    float acc[4][4][4];
    #pragma unroll
    for (int i = 0; i < 4; i++)
        #pragma unroll
        for (int j = 0; j < 4; j++)
            #pragma unroll
            for (int r = 0; r < 4; r++) acc[i][j][r] = 0.f;

    float4 ra[2], rb[2];

    #define G2_LOAD(k0)                                                          \
        _Pragma("unroll")                                                        \
        for (int i = 0; i < 2; i++) {                                            \
            int f = tid + i * 256;                                               \
            int m = f >> 2, q = f & 3;                                           \
            ra[i] = *(const float4*)(Hb + (size_t)(n0 + m) * E_ + (k0) + q*4);   \
            int k = f >> 5, c = f & 31;                                          \
            rb[i] = *(const float4*)(Mb + (size_t)((k0) + k) * C_ + c * 4);      \
        }
    #define G2_STORE(buf)                                                        \
        _Pragma("unroll")                                                        \
        for (int i = 0; i < 2; i++) {                                            \
            int f = tid + i * 256;                                               \
            int m = f >> 2, q = f & 3;                                           \
            As[buf][q * 4 + 0][m] = tf32r(ra[i].x);                              \
            As[buf][q * 4 + 1][m] = tf32r(ra[i].y);                              \
            As[buf][q * 4 + 2][m] = tf32r(ra[i].z);                              \
            As[buf][q * 4 + 3][m] = tf32r(ra[i].w);                              \
            int k = f >> 5, c = f & 31;                                          \
            float4 v = rb[i];                                                    \
            v.x = tf32r(v.x); v.y = tf32r(v.y); v.z = tf32r(v.z); v.w = tf32r(v.w);\
            *(float4*)&Bs[buf][k][c * 4] = v;                                    \
        }

    G2_LOAD(0); G2_STORE(0); __syncthreads();
    const int KT = E_ / 16;
    for (int kt = 0; kt < KT; ++kt) {
        int cur = kt & 1;
        if (kt + 1 < KT) { G2_LOAD((kt + 1) * 16); }
        MMA_TILE(cur);
        if (kt + 1 < KT) { G2_STORE(cur ^ 1); }
        __syncthreads();
    }

    float* Ob = outp + (size_t)b * N_ * C_;
    #pragma unroll
    for (int mt = 0; mt < 4; mt++) {
        int rr = wm * 64 + mt * 16 + g;
        float sa = dvS[rr], sb = dvS[rr + 8];
        #pragma unroll
        for (int nt = 0; nt < 4; nt++) {
            int col = wn * 32 + nt * 8 + tg * 2;
            float b0 = biasS[col], b1 = biasS[col + 1];
            float2 v0 = make_float2(acc[mt][nt][0] * sa + b0, acc[mt][nt][1] * sa + b1);
            float2 v1 = make_float2(acc[mt][nt][2] * sb + b0, acc[mt][nt][3] * sb + b1);
            *(float2*)(Ob + (size_t)(n0 + rr) * C_ + col)     = v0;
            *(float2*)(Ob + (size_t)(n0 + rr + 8) * C_ + col) = v1;
        }
    }
}

// ---------------- launch ----------------------------------------------------
extern "C" void kernel_launch(void* const* d_in, const int* in_sizes, int n_in,
                              void* d_out, int out_size) {
    const float *x = nullptr, *H = nullptr, *W = nullptr, *bias = nullptr;
    for (int i = 0; i < n_in; i++) {
        long long s = in_sizes[i];
        if (s == (long long)B_ * N_ * E_)      H = (const float*)d_in[i];
        else if (s == (long long)B_ * N_ * C_) x = (const float*)d_in[i];
        else if (s == (long long)C_ * C_)      W = (const float*)d_in[i];
        else if (s == (long long)C_)           bias = (const float*)d_in[i];
    }
    float* outp = (float*)d_out;

    dv_kernel<<<B_ * N_ / 8, dim3(32, 8)>>>(H);
    wt_kernel<<<C_ * C_ / 256, 256>>>(W);

    // M = De^-1 H^T (Dv^-1/2 x), De fused
    gemm1_kernel<<<dim3(E_ / 128, 1, B_), 256>>>(H, x);
    // M2 = M W^T
    gemm1b_kernel<<<(B_ * E_) / 128, 256>>>();
    // out = Dv^-1/2 (H M2) + b
    gemm2_kernel<<<dim3(N_ / 128, 1, B_), 256>>>(H, bias, outp);
}

// round 8
// speedup vs baseline: 2.9746x; 1.4155x over previous
#include <cuda_runtime.h>
#include <cstdint>

// BatchedHGNNLayer: out = diag(Dv^-1/2) H diag(De^-1) H^T diag(Dv^-1/2) x W^T + b
// B=8, N=4096, E=2048, C=128 fp32. mma.sync tf32 + cp.async 4-stage pipelines.

#define B_ 8
#define N_ 4096
#define E_ 2048
#define C_ 128
#define EPS 1e-6f
#define STG 4

// ---------------- scratch (device globals; no cudaMalloc) -------------------
__device__ float g_DvInv[B_ * N_];
__device__ float g_Hr[(size_t)B_ * N_ * E_];    // rna-rounded H, same layout
__device__ float g_Xs[(size_t)B_ * N_ * C_];    // rna(x * DvInv)
__device__ float g_Wr[C_ * C_];                 // rna(W)
__device__ float g_M[(size_t)B_ * E_ * C_];     // rna(De^-1 H^T Xs)   [b][e][c]
__device__ float g_M2T[(size_t)B_ * C_ * E_];   // rna((M W^T)^T)      [b][c2][e]

// ---------------- helpers ----------------------------------------------------
__device__ __forceinline__ float tf32r(float x) {
    uint32_t u;
    asm("cvt.rna.tf32.f32 %0, %1;" : "=r"(u) : "f"(x));
    return __uint_as_float(u);
}
__device__ __forceinline__ uint32_t smem_u32(const void* p) {
    uint32_t a;
    asm("{ .reg .u64 t; cvta.to.shared.u64 t, %1; cvt.u32.u64 %0, t; }" : "=r"(a) : "l"(p));
    return a;
}
__device__ __forceinline__ void mma_tf32(float* c, const uint32_t* a, const uint32_t* b) {
    asm volatile(
        "mma.sync.aligned.m16n8k8.row.col.f32.tf32.tf32.f32 "
        "{%0,%1,%2,%3}, {%4,%5,%6,%7}, {%8,%9}, {%0,%1,%2,%3};"
        : "+f"(c[0]), "+f"(c[1]), "+f"(c[2]), "+f"(c[3])
        : "r"(a[0]), "r"(a[1]), "r"(a[2]), "r"(a[3]), "r"(b[0]), "r"(b[1]));
}
#define CP16(dst, src) \
    asm volatile("cp.async.cg.shared.global [%0], [%1], 16;" :: "r"(dst), "l"(src))
#define CP_COMMIT() asm volatile("cp.async.commit_group;" ::: "memory")
#define CP_WAIT(n)  asm volatile("cp.async.wait_group %0;" :: "n"(n) : "memory")
#define FU(x) __float_as_uint(x)

// ---------------- prep kernels ----------------------------------------------
// H -> g_Hr (rna) + Dv row sums (exact). One warp per row.
__global__ void prep_h(const float* __restrict__ Hg) {
    int row = blockIdx.x * 8 + threadIdx.y;   // flattened b*N + n
    const float4* src = (const float4*)(Hg + (size_t)row * E_);
    float4* dst = (float4*)(g_Hr + (size_t)row * E_);
    float s = 0.f;
    for (int i = threadIdx.x; i < E_ / 4; i += 32) {
        float4 v = src[i];
        s += (v.x + v.y) + (v.z + v.w);
        float4 r;
        r.x = tf32r(v.x); r.y = tf32r(v.y); r.z = tf32r(v.z); r.w = tf32r(v.w);
        dst[i] = r;
    }
    #pragma unroll
    for (int o = 16; o; o >>= 1) s += __shfl_xor_sync(0xffffffffu, s, o);
    if (threadIdx.x == 0) g_DvInv[row] = rsqrtf(s + EPS);
}

// g_Xs = rna(x * DvInv)
__global__ void prep_x(const float* __restrict__ xg) {
    int i = blockIdx.x * 256 + threadIdx.x;            // f4 index
    int row = i >> 5;                                  // C_/4 = 32 f4 per row
    float dv = g_DvInv[row];
    float4 v = ((const float4*)xg)[i];
    float4 r;
    r.x = tf32r(v.x * dv); r.y = tf32r(v.y * dv);
    r.z = tf32r(v.z * dv); r.w = tf32r(v.w * dv);
    ((float4*)g_Xs)[i] = r;
}

__global__ void prep_w(const float* __restrict__ Wg) {
    int i = blockIdx.x * 256 + threadIdx.x;            // 4096 f4
    float4 v = ((const float4*)Wg)[i];
    float4 r;
    r.x = tf32r(v.x); r.y = tf32r(v.y); r.z = tf32r(v.z); r.w = tf32r(v.w);
    ((float4*)g_Wr)[i] = r;
}

// ---------------- unified cp.async tf32 GEMM ---------------------------------
// D[128m][128n] = sum_k A[m][k] * B[n][k].  BK=32, 4-stage cp.async.
// MODE 1 (KM layout): A-tile = g_Hr rows (k=n, cols e-tile), B = g_Xs rows.
//        Fused De (column sums of A tiles). Out: g_M[e][c] (rna, * 1/De).
// MODE 2 (MK): A = g_Wr [c2][c], B = g_M e-tile rows [e][c]. Out: g_M2T[c2][e] (rna).
// MODE 3 (MK): A = g_Hr n-tile rows [n][e], B = g_M2T [c][e].
//        Out: d_out[n][c] = acc * DvInv[n] + bias[c].
template <int MODE>
__global__ __launch_bounds__(256, 1) void gemm_cp(float* __restrict__ Og,
                                                  const float* __restrict__ biasg) {
    constexpr int KLEN = (MODE == 1) ? N_ : ((MODE == 2) ? C_ : E_);
    constexpr bool KM = (MODE == 1);
    constexpr int SA = KM ? 136 : 36;                  // smem stride in floats
    constexpr int TILE = KM ? (32 * 136 * 4) : (128 * 36 * 4);

    extern __shared__ __align__(16) char ds[];
    __shared__ float deP[2][128];
    __shared__ float scl[128];

    const int tid = threadIdx.x, b = blockIdx.z, blk = blockIdx.x;
    const int lane = tid & 31, wid = tid >> 5;
    const int g = lane >> 2, tg = lane & 3;
    const int wm = wid & 1, wn = wid >> 1;

    const float* Ag; const float* Bg;
    int lda, ldb, acol = 0;
    if constexpr (MODE == 1) {
        Ag = g_Hr + (size_t)b * N_ * E_; lda = E_; acol = blk * 128;
        Bg = g_Xs + (size_t)b * N_ * C_; ldb = C_;
    } else if constexpr (MODE == 2) {
        Ag = g_Wr; lda = C_;
        Bg = g_M + ((size_t)b * E_ + blk * 128) * C_; ldb = C_;
    } else {
        Ag = g_Hr + ((size_t)b * N_ + blk * 128) * E_; lda = E_;
        Bg = g_M2T + (size_t)b * C_ * E_; ldb = E_;
    }

    if (MODE == 3 && tid < 128) scl[tid] = biasg[tid];

    const uint32_t sA = smem_u32(ds), sB = sA + STG * TILE;

    float acc[4][4][4];
    #pragma unroll
    for (int i = 0; i < 4; i++)
        #pragma unroll
        for (int j = 0; j < 4; j++)
            #pragma unroll
            for (int r = 0; r < 4; r++) acc[i][j][r] = 0.f;

    float deacc = 0.f;
    const int mcol = tid & 127, half = tid >> 7;

    auto issue = [&](int kt) {
        int buf = kt & 3;
        if (KM) {
            #pragma unroll
            for (int i = 0; i < 4; i++) {
                int ch = tid + 256 * i;
                int k = ch >> 5, m4 = (ch & 31) * 4;
                CP16(sA + buf * TILE + (k * SA + m4) * 4,
                     Ag + (size_t)(kt * 32 + k) * lda + acol + m4);
                CP16(sB + buf * TILE + (k * SA + m4) * 4,
                     Bg + (size_t)(kt * 32 + k) * ldb + m4);
            }
        } else {
            #pragma unroll
            for (int i = 0; i < 4; i++) {
                int ch = tid + 256 * i;
                int m = ch >> 3, k4 = (ch & 7) * 4;
                CP16(sA + buf * TILE + (m * SA + k4) * 4,
                     Ag + (size_t)m * lda + kt * 32 + k4);
                CP16(sB + buf * TILE + (m * SA + k4) * 4,
                     Bg + (size_t)m * ldb + kt * 32 + k4);
            }
        }
        CP_COMMIT();
    };

    const int KT = KLEN / 32;
    issue(0);
    if (KT > 1) issue(1);
    if (KT > 2) issue(2);

    for (int kt = 0; kt < KT; kt++) {
        if (kt + 3 < KT) issue(kt + 3);
        int rem = KT - 1 - kt;
        if (rem >= 3)      CP_WAIT(3);
        else if (rem == 2) CP_WAIT(2);
        else if (rem == 1) CP_WAIT(1);
        else               CP_WAIT(0);
        __syncthreads();

        const float* As = (const float*)(ds + (size_t)(kt & 3) * TILE);
        const float* Bs = (const float*)(ds + (size_t)STG * TILE + (size_t)(kt & 3) * TILE);

        if (MODE == 1) {  // fused De: column sums of the exact(-ly rounded) H tile
            float s = 0.f;
            #pragma unroll
            for (int k = 0; k < 16; k++) s += As[(half * 16 + k) * SA + mcol];
            deacc += s;
        }

        #pragma unroll
        for (int ks = 0; ks < 32; ks += 8) {
            uint32_t af[4][4], bf[4][2];
            #pragma unroll
            for (int mt = 0; mt < 4; mt++) {
                int m = wm * 64 + mt * 16 + g;
                if (KM) {
                    af[mt][0] = FU(As[(ks + tg) * SA + m]);
                    af[mt][1] = FU(As[(ks + tg) * SA + m + 8]);
                    af[mt][2] = FU(As[(ks + tg + 4) * SA + m]);
                    af[mt][3] = FU(As[(ks + tg + 4) * SA + m + 8]);
                } else {
                    af[mt][0] = FU(As[m * SA + ks + tg]);
                    af[mt][1] = FU(As[(m + 8) * SA + ks + tg]);
                    af[mt][2] = FU(As[m * SA + ks + tg + 4]);
                    af[mt][3] = FU(As[(m + 8) * SA + ks + tg + 4]);
                }
            }
            #pragma unroll
            for (int nt = 0; nt < 4; nt++) {
                int n = wn * 32 + nt * 8 + g;
                if (KM) {
                    bf[nt][0] = FU(Bs[(ks + tg) * SA + n]);
                    bf[nt][1] = FU(Bs[(ks + tg + 4) * SA + n]);
                } else {
                    bf[nt][0] = FU(Bs[n * SA + ks + tg]);
                    bf[nt][1] = FU(Bs[n * SA + ks + tg + 4]);
                }
            }
            #pragma unroll
            for (int mt = 0; mt < 4; mt++)
                #pragma unroll
                for (int nt = 0; nt < 4; nt++)
                    mma_tf32(acc[mt][nt], af[mt], bf[nt]);
        }
        __syncthreads();
    }

    if (MODE == 1) {  // deterministic De combine
        deP[half][mcol] = deacc;
        __syncthreads();
        if (tid < 128) scl[tid] = 1.0f / (deP[0][tid] + deP[1][tid] + EPS);
        __syncthreads();
    }

    #pragma unroll
    for (int mt = 0; mt < 4; mt++) {
        int r = wm * 64 + mt * 16 + g;
        #pragma unroll
        for (int nt = 0; nt < 4; nt++) {
            int col = wn * 32 + nt * 8 + tg * 2;
            float* c = acc[mt][nt];
            if (MODE == 1) {
                float s0 = scl[r], s1 = scl[r + 8];
                float2 v0 = make_float2(tf32r(c[0] * s0), tf32r(c[1] * s0));
                float2 v1 = make_float2(tf32r(c[2] * s1), tf32r(c[3] * s1));
                *(float2*)(g_M + ((size_t)b * E_ + blk * 128 + r) * C_ + col) = v0;
                *(float2*)(g_M + ((size_t)b * E_ + blk * 128 + r + 8) * C_ + col) = v1;
            } else if (MODE == 2) {
                float2 v0 = make_float2(tf32r(c[0]), tf32r(c[1]));
                float2 v1 = make_float2(tf32r(c[2]), tf32r(c[3]));
                *(float2*)(g_M2T + ((size_t)b * C_ + r) * E_ + blk * 128 + col) = v0;
                *(float2*)(g_M2T + ((size_t)b * C_ + r + 8) * E_ + blk * 128 + col) = v1;
            } else {
                float s0 = g_DvInv[b * N_ + blk * 128 + r];
                float s1 = g_DvInv[b * N_ + blk * 128 + r + 8];
                float b0 = scl[col], b1 = scl[col + 1];
                float2 v0 = make_float2(c[0] * s0 + b0, c[1] * s0 + b1);
                float2 v1 = make_float2(c[2] * s1 + b0, c[3] * s1 + b1);
                *(float2*)(Og + ((size_t)b * N_ + blk * 128 + r) * C_ + col) = v0;
                *(float2*)(Og + ((size_t)b * N_ + blk * 128 + r + 8) * C_ + col) = v1;
            }
        }
    }
}

// ---------------- launch -----------------------------------------------------
extern "C" void kernel_launch(void* const* d_in, const int* in_sizes, int n_in,
                              void* d_out, int out_size) {
    const float *x = nullptr, *H = nullptr, *W = nullptr, *bias = nullptr;
    for (int i = 0; i < n_in; i++) {
        long long s = in_sizes[i];
        if (s == (long long)B_ * N_ * E_)      H = (const float*)d_in[i];
        else if (s == (long long)B_ * N_ * C_) x = (const float*)d_in[i];
        else if (s == (long long)C_ * C_)      W = (const float*)d_in[i];
        else if (s == (long long)C_)           bias = (const float*)d_in[i];
    }
    float* outp = (float*)d_out;

    const int DYN1 = STG * 2 * (32 * 136 * 4);    // 139264
    const int DYNM = STG * 2 * (128 * 36 * 4);    // 147456
    cudaFuncSetAttribute(gemm_cp<1>, cudaFuncAttributeMaxDynamicSharedMemorySize, DYN1);
    cudaFuncSetAttribute(gemm_cp<2>, cudaFuncAttributeMaxDynamicSharedMemorySize, DYNM);
    cudaFuncSetAttribute(gemm_cp<3>, cudaFuncAttributeMaxDynamicSharedMemorySize, DYNM);

    // prep: H_rna + Dv (one H pass), then x scale+rna, W rna
    prep_h<<<B_ * N_ / 8, dim3(32, 8)>>>(H);
    prep_x<<<(B_ * N_ * C_ / 4) / 256, 256>>>(x);
    prep_w<<<(C_ * C_ / 4) / 256, 256>>>(W);

    // M = De^-1 H^T (Dv^-1/2 x)
    gemm_cp<1><<<dim3(E_ / 128, 1, B_), 256, DYN1>>>(nullptr, nullptr);
    // M2T = W M^T
    gemm_cp<2><<<dim3(E_ / 128, 1, B_), 256, DYNM>>>(nullptr, nullptr);
    // out = Dv^-1/2 (H M2) + bias
    gemm_cp<3><<<dim3(N_ / 128, 1, B_), 256, DYNM>>>(outp, bias);
}

// round 9
// speedup vs baseline: 3.1975x; 1.0750x over previous
#include <cuda_runtime.h>
#include <cstdint>

// BatchedHGNNLayer: out = diag(Dv^-1/2) H diag(De^-1) H^T diag(Dv^-1/2) x W^T + b
// B=8, N=4096, E=2048, C=128 fp32. mma.sync tf32 + cp.async, raw-H streaming,
// gemm1b fused into gemm1 epilogue.

#define B_ 8
#define N_ 4096
#define E_ 2048
#define C_ 128
#define EPS 1e-6f
#define STG 4

// ---------------- scratch ----------------------------------------------------
__device__ float g_DvInv[B_ * N_];
__device__ float g_Xs[(size_t)B_ * N_ * C_];    // rna(x * DvInv)
__device__ float g_M2T[(size_t)B_ * C_ * E_];   // rna((De^-1 H^T Xs) W^T)^T  [b][c2][e]

// ---------------- helpers ----------------------------------------------------
__device__ __forceinline__ float tf32r(float x) {
    uint32_t u;
    asm("cvt.rna.tf32.f32 %0, %1;" : "=r"(u) : "f"(x));
    return __uint_as_float(u);
}
__device__ __forceinline__ uint32_t tf32u(float x) {
    uint32_t u;
    asm("cvt.rna.tf32.f32 %0, %1;" : "=r"(u) : "f"(x));
    return u;
}
__device__ __forceinline__ uint32_t smem_u32(const void* p) {
    uint32_t a;
    asm("{ .reg .u64 t; cvta.to.shared.u64 t, %1; cvt.u32.u64 %0, t; }" : "=r"(a) : "l"(p));
    return a;
}
__device__ __forceinline__ void mma_tf32(float* c, const uint32_t* a, const uint32_t* b) {
    asm volatile(
        "mma.sync.aligned.m16n8k8.row.col.f32.tf32.tf32.f32 "
        "{%0,%1,%2,%3}, {%4,%5,%6,%7}, {%8,%9}, {%0,%1,%2,%3};"
        : "+f"(c[0]), "+f"(c[1]), "+f"(c[2]), "+f"(c[3])
        : "r"(a[0]), "r"(a[1]), "r"(a[2]), "r"(a[3]), "r"(b[0]), "r"(b[1]));
}
#define CP16(dst, src) \
    asm volatile("cp.async.cg.shared.global [%0], [%1], 16;" :: "r"(dst), "l"(src))
#define CP_COMMIT() asm volatile("cp.async.commit_group;" ::: "memory")
#define CP_WAIT(n)  asm volatile("cp.async.wait_group %0;" :: "n"(n) : "memory")
#define FU(x) __float_as_uint(x)

// ---------------- small kernels ----------------------------------------------
// Dv from raw H (one warp per row).
__global__ void dv_kernel(const float* __restrict__ Hg) {
    int row = blockIdx.x * 8 + threadIdx.y;   // flattened b*N + n
    const float4* src = (const float4*)(Hg + (size_t)row * E_);
    float s = 0.f;
    for (int i = threadIdx.x; i < E_ / 4; i += 32) {
        float4 v = src[i];
        s += (v.x + v.y) + (v.z + v.w);
    }
    #pragma unroll
    for (int o = 16; o; o >>= 1) s += __shfl_xor_sync(0xffffffffu, s, o);
    if (threadIdx.x == 0) g_DvInv[row] = rsqrtf(s + EPS);
}

// g_Xs = rna(x * DvInv)
__global__ void prep_x(const float* __restrict__ xg) {
    int i = blockIdx.x * 256 + threadIdx.x;            // f4 index
    int row = i >> 5;                                  // 32 f4 per row
    float dv = g_DvInv[row];
    float4 v = ((const float4*)xg)[i];
    float4 r;
    r.x = tf32r(v.x * dv); r.y = tf32r(v.y * dv);
    r.z = tf32r(v.z * dv); r.w = tf32r(v.w * dv);
    ((float4*)g_Xs)[i] = r;
}

// ---------------- main GEMM kernels ------------------------------------------
// MODE 1: KM layout. A = raw H cols (k=n, m=e-tile), B = g_Xs rows (k=n, n=c).
//   Fused: De (raw-H column sums), then in-CTA sub-GEMM M2T = W M^T. Out: g_M2T.
// MODE 3: MK layout. A = raw H n-tile rows (m=n, k=e), B = g_M2T (n=c2, k=e).
//   Out: d_out[n][c] = acc * DvInv[n] + bias[c].
template <int MODE>
__global__ __launch_bounds__(256, 1) void gemm_cp(const float* __restrict__ Hg,
                                                  const float* __restrict__ Wg,
                                                  float* __restrict__ Og,
                                                  const float* __restrict__ biasg) {
    constexpr int KLEN = (MODE == 1) ? N_ : E_;
    constexpr bool KM = (MODE == 1);
    constexpr int SA = KM ? 136 : 36;
    constexpr int TILE = KM ? (32 * 136 * 4) : (128 * 36 * 4);

    extern __shared__ __align__(16) char ds[];
    __shared__ float deP[2][128];
    __shared__ float scl[128];

    const int tid = threadIdx.x, b = blockIdx.z, blk = blockIdx.x;
    const int lane = tid & 31, wid = tid >> 5;
    const int g = lane >> 2, tg = lane & 3;
    const int wm = wid & 1, wn = wid >> 1;

    const float* Ag; const float* Bg;
    int lda, ldb, acol = 0;
    if constexpr (MODE == 1) {
        Ag = Hg + (size_t)b * N_ * E_; lda = E_; acol = blk * 128;
        Bg = g_Xs + (size_t)b * N_ * C_; ldb = C_;
    } else {
        Ag = Hg + ((size_t)b * N_ + blk * 128) * E_; lda = E_;
        Bg = g_M2T + (size_t)b * C_ * E_; ldb = E_;
    }

    if (MODE == 3 && tid < 128) scl[tid] = biasg[tid];

    const uint32_t sA = smem_u32(ds), sB = sA + STG * TILE;

    float acc[4][4][4];
    #pragma unroll
    for (int i = 0; i < 4; i++)
        #pragma unroll
        for (int j = 0; j < 4; j++)
            #pragma unroll
            for (int r = 0; r < 4; r++) acc[i][j][r] = 0.f;

    float deacc = 0.f;
    const int mcol = tid & 127, half = tid >> 7;

    auto issue = [&](int kt) {
        int buf = kt & 3;
        if (KM) {
            #pragma unroll
            for (int i = 0; i < 4; i++) {
                int ch = tid + 256 * i;
                int k = ch >> 5, m4 = (ch & 31) * 4;
                CP16(sA + buf * TILE + (k * SA + m4) * 4,
                     Ag + (size_t)(kt * 32 + k) * lda + acol + m4);
                CP16(sB + buf * TILE + (k * SA + m4) * 4,
                     Bg + (size_t)(kt * 32 + k) * ldb + m4);
            }
        } else {
            #pragma unroll
            for (int i = 0; i < 4; i++) {
                int ch = tid + 256 * i;
                int m = ch >> 3, k4 = (ch & 7) * 4;
                CP16(sA + buf * TILE + (m * SA + k4) * 4,
                     Ag + (size_t)m * lda + kt * 32 + k4);
                CP16(sB + buf * TILE + (m * SA + k4) * 4,
                     Bg + (size_t)m * ldb + kt * 32 + k4);
            }
        }
        CP_COMMIT();
    };

    const int KT = KLEN / 32;
    issue(0); issue(1); issue(2);

    for (int kt = 0; kt < KT; kt++) {
        if (kt + 3 < KT) issue(kt + 3);
        int rem = KT - 1 - kt;
        if (rem >= 3)      CP_WAIT(3);
        else if (rem == 2) CP_WAIT(2);
        else if (rem == 1) CP_WAIT(1);
        else               CP_WAIT(0);
        __syncthreads();

        const float* As = (const float*)(ds + (size_t)(kt & 3) * TILE);
        const float* Bs = (const float*)(ds + (size_t)STG * TILE + (size_t)(kt & 3) * TILE);

        if (MODE == 1) {  // fused De from RAW H (matches reference exactly)
            float s = 0.f;
            #pragma unroll
            for (int k = 0; k < 16; k++) s += As[(half * 16 + k) * SA + mcol];
            deacc += s;
        }

        #pragma unroll
        for (int ks = 0; ks < 32; ks += 8) {
            uint32_t af[4][4], bf[4][2];
            #pragma unroll
            for (int mt = 0; mt < 4; mt++) {
                int m = wm * 64 + mt * 16 + g;
                if (KM) {  // raw H -> rna at frag load
                    af[mt][0] = tf32u(As[(ks + tg) * SA + m]);
                    af[mt][1] = tf32u(As[(ks + tg) * SA + m + 8]);
                    af[mt][2] = tf32u(As[(ks + tg + 4) * SA + m]);
                    af[mt][3] = tf32u(As[(ks + tg + 4) * SA + m + 8]);
                } else {
                    af[mt][0] = tf32u(As[m * SA + ks + tg]);
                    af[mt][1] = tf32u(As[(m + 8) * SA + ks + tg]);
                    af[mt][2] = tf32u(As[m * SA + ks + tg + 4]);
                    af[mt][3] = tf32u(As[(m + 8) * SA + ks + tg + 4]);
                }
            }
            #pragma unroll
            for (int nt = 0; nt < 4; nt++) {
                int n = wn * 32 + nt * 8 + g;
                if (KM) {  // B pre-rounded
                    bf[nt][0] = FU(Bs[(ks + tg) * SA + n]);
                    bf[nt][1] = FU(Bs[(ks + tg + 4) * SA + n]);
                } else {
                    bf[nt][0] = FU(Bs[n * SA + ks + tg]);
                    bf[nt][1] = FU(Bs[n * SA + ks + tg + 4]);
                }
            }
            #pragma unroll
            for (int mt = 0; mt < 4; mt++)
                #pragma unroll
                for (int nt = 0; nt < 4; nt++)
                    mma_tf32(acc[mt][nt], af[mt], bf[nt]);
        }
        __syncthreads();
    }

    if constexpr (MODE == 1) {
        // ---- start W load into B-ring region (free after final sync) ----
        float* Wsm = (float*)(ds + STG * TILE);          // [128][132]
        float* Msm = (float*)ds;                         // [128][132]
        {
            const uint32_t sW = smem_u32(Wsm);
            #pragma unroll
            for (int i = 0; i < 16; i++) {
                int ch = tid + 256 * i;                  // 4096 chunks = 128 x 32
                int m = ch >> 5, q = ch & 31;
                CP16(sW + (m * 132 + q * 4) * 4, Wg + (size_t)m * C_ + q * 4);
            }
            CP_COMMIT();
        }
        // ---- De combine (deterministic) ----
        deP[half][mcol] = deacc;
        __syncthreads();
        if (tid < 128) scl[tid] = 1.0f / (deP[0][tid] + deP[1][tid] + EPS);
        __syncthreads();
        // ---- dump De-scaled rounded M tile into A-ring region ----
        #pragma unroll
        for (int mt = 0; mt < 4; mt++) {
            int r = wm * 64 + mt * 16 + g;
            float s0 = scl[r], s1 = scl[r + 8];
            #pragma unroll
            for (int nt = 0; nt < 4; nt++) {
                int col = wn * 32 + nt * 8 + tg * 2;
                float* c = acc[mt][nt];
                *(float2*)(Msm + r * 132 + col) =
                    make_float2(tf32r(c[0] * s0), tf32r(c[1] * s0));
                *(float2*)(Msm + (r + 8) * 132 + col) =
                    make_float2(tf32r(c[2] * s1), tf32r(c[3] * s1));
            }
        }
        CP_WAIT(0);
        __syncthreads();
        // ---- in-CTA sub-GEMM: M2T[c2][e] = sum_c W[c2][c] * M[e][c] ----
        #pragma unroll
        for (int i = 0; i < 4; i++)
            #pragma unroll
            for (int j = 0; j < 4; j++)
                #pragma unroll
                for (int r = 0; r < 4; r++) acc[i][j][r] = 0.f;
        for (int ks = 0; ks < 128; ks += 8) {
            uint32_t af[4][4], bf[4][2];
            #pragma unroll
            for (int mt = 0; mt < 4; mt++) {
                int m = wm * 64 + mt * 16 + g;
                af[mt][0] = tf32u(Wsm[m * 132 + ks + tg]);
                af[mt][1] = tf32u(Wsm[(m + 8) * 132 + ks + tg]);
                af[mt][2] = tf32u(Wsm[m * 132 + ks + tg + 4]);
                af[mt][3] = tf32u(Wsm[(m + 8) * 132 + ks + tg + 4]);
            }
            #pragma unroll
            for (int nt = 0; nt < 4; nt++) {
                int n = wn * 32 + nt * 8 + g;
                bf[nt][0] = FU(Msm[n * 132 + ks + tg]);
                bf[nt][1] = FU(Msm[n * 132 + ks + tg + 4]);
            }
            #pragma unroll
            for (int mt = 0; mt < 4; mt++)
                #pragma unroll
                for (int nt = 0; nt < 4; nt++)
                    mma_tf32(acc[mt][nt], af[mt], bf[nt]);
        }
        // ---- write M2T (rounded; feeds gemm<3> as tf32 operand) ----
        #pragma unroll
        for (int mt = 0; mt < 4; mt++) {
            int r = wm * 64 + mt * 16 + g;   // c2
            #pragma unroll
            for (int nt = 0; nt < 4; nt++) {
                int col = wn * 32 + nt * 8 + tg * 2;   // e within tile
                float* c = acc[mt][nt];
                *(float2*)(g_M2T + ((size_t)b * C_ + r) * E_ + blk * 128 + col) =
                    make_float2(tf32r(c[0]), tf32r(c[1]));
                *(float2*)(g_M2T + ((size_t)b * C_ + r + 8) * E_ + blk * 128 + col) =
                    make_float2(tf32r(c[2]), tf32r(c[3]));
            }
        }
    } else {
        // ---- MODE 3 epilogue: Dv scale + bias, straight to d_out ----
        #pragma unroll
        for (int mt = 0; mt < 4; mt++) {
            int r = wm * 64 + mt * 16 + g;
            float s0 = g_DvInv[b * N_ + blk * 128 + r];
            float s1 = g_DvInv[b * N_ + blk * 128 + r + 8];
            #pragma unroll
            for (int nt = 0; nt < 4; nt++) {
                int col = wn * 32 + nt * 8 + tg * 2;
                float b0 = scl[col], b1 = scl[col + 1];
                float* c = acc[mt][nt];
                *(float2*)(Og + ((size_t)b * N_ + blk * 128 + r) * C_ + col) =
                    make_float2(c[0] * s0 + b0, c[1] * s0 + b1);
                *(float2*)(Og + ((size_t)b * N_ + blk * 128 + r + 8) * C_ + col) =
                    make_float2(c[2] * s1 + b0, c[3] * s1 + b1);
            }
        }
    }
}

// ---------------- launch -----------------------------------------------------
extern "C" void kernel_launch(void* const* d_in, const int* in_sizes, int n_in,
                              void* d_out, int out_size) {
    const float *x = nullptr, *H = nullptr, *W = nullptr, *bias = nullptr;
    for (int i = 0; i < n_in; i++) {
        long long s = in_sizes[i];
        if (s == (long long)B_ * N_ * E_)      H = (const float*)d_in[i];
        else if (s == (long long)B_ * N_ * C_) x = (const float*)d_in[i];
        else if (s == (long long)C_ * C_)      W = (const float*)d_in[i];
        else if (s == (long long)C_)           bias = (const float*)d_in[i];
    }
    float* outp = (float*)d_out;

    const int DYN1 = STG * 2 * (32 * 136 * 4);    // 139264 (>= 2 * 128*132*4 for epilogue)
    const int DYN3 = STG * 2 * (128 * 36 * 4);    // 147456
    cudaFuncSetAttribute(gemm_cp<1>, cudaFuncAttributeMaxDynamicSharedMemorySize, DYN1);
    cudaFuncSetAttribute(gemm_cp<3>, cudaFuncAttributeMaxDynamicSharedMemorySize, DYN3);

    dv_kernel<<<B_ * N_ / 8, dim3(32, 8)>>>(H);
    prep_x<<<(B_ * N_ * C_ / 4) / 256, 256>>>(x);

    // M2T = W (De^-1 H^T (Dv^-1/2 x))^T   [gemm1 + fused gemm1b]
    gemm_cp<1><<<dim3(E_ / 128, 1, B_), 256, DYN1>>>(H, W, nullptr, nullptr);
    // out = Dv^-1/2 (H M2) + bias
    gemm_cp<3><<<dim3(N_ / 128, 1, B_), 256, DYN3>>>(H, nullptr, outp, bias);
}